// round 17
// baseline (speedup 1.0000x reference)
#include <cuda_runtime.h>
#include <cuda_bf16.h>
#include <cstdint>

// Problem constants
#define BATCH   32
#define NSET    16384
#define DIM     128
#define CHUNKS  128
#define TILE_M  128
#define TILES_PER_CTA 2

#define LDBYTES 272          // bf16 A-tile row stride in bytes (136 elems)
#define ABUF    34816        // one A buffer (128 rows * 272 B)

// ---------------------------------------------------------------------------
// Device scratch (static; no runtime allocation)
// ---------------------------------------------------------------------------
__device__ float g_partial[BATCH * CHUNKS * DIM];        // 2 MB
__device__ float g_pooled[BATCH * DIM];                  // 16 KB
__device__ uint2 g_xbf[(size_t)BATCH * NSET * 32];       // 128 MB: x as bf16 linear
// w1 in MMA-B fragment order (verified): block (npair 0..7, kstep 0..7):
//   lane uint4 = {b0(n0), b1(n0), b0(n0+8), b1(n0+8)}, n0 = npair*16 + lane/4,
//   b0 = w1[k0][n],w1[k0+1][n]; b1 = same at k0+8; k0 = kstep*16 + (lane%4)*2
__device__ uint4 g_w1frag[2048];                         // 32 KB

// ---------------------------------------------------------------------------
// Helpers
// ---------------------------------------------------------------------------
#define DI __device__ __forceinline__

DI uint32_t smem_u32(const void* p) {
    uint32_t a;
    asm("{ .reg .u64 t; cvta.to.shared.u64 t, %1; cvt.u32.u64 %0, t; }"
        : "=r"(a) : "l"(p));
    return a;
}

DI uint32_t bf16x2(float lo, float hi) {
    uint32_t r;
    asm("cvt.rn.bf16x2.f32 %0, %1, %2;" : "=r"(r) : "f"(hi), "f"(lo));
    return r;
}

#define LDSM_X4(r, addr)                                                      \
    asm volatile("ldmatrix.sync.aligned.m8n8.x4.shared.b16 {%0,%1,%2,%3}, [%4];" \
                 : "=r"((r)[0]), "=r"((r)[1]), "=r"((r)[2]), "=r"((r)[3])     \
                 : "r"(addr))

#define MMA16816(c, a, b0, b1)                                                \
    asm volatile("mma.sync.aligned.m16n8k16.row.col.f32.bf16.bf16.f32 "       \
                 "{%0,%1,%2,%3}, {%4,%5,%6,%7}, {%8,%9}, {%0,%1,%2,%3};"      \
                 : "+f"((c)[0]), "+f"((c)[1]), "+f"((c)[2]), "+f"((c)[3])     \
                 : "r"((a)[0]), "r"((a)[1]), "r"((a)[2]), "r"((a)[3]),        \
                   "r"(b0), "r"(b1))

// ---------------------------------------------------------------------------
// Pass 1: partial column-sums + bf16 conversion of x.  [verified 55us, 82% DRAM]
// ---------------------------------------------------------------------------
__global__ void __launch_bounds__(256)
sum_cvt_kernel(const float* __restrict__ x) {
    const int b = blockIdx.y, chunk = blockIdx.x;
    const int tid = threadIdx.x, w8 = tid >> 5, l = tid & 31;
    const size_t base = (size_t)(b * NSET + chunk * TILE_M) * 32;
    const float4* xt = reinterpret_cast<const float4*>(x) + base;
    uint2* xb = g_xbf + base;

    float4 acc = make_float4(0.f, 0.f, 0.f, 0.f);
#pragma unroll
    for (int i = 0; i < 16; i++) {
        const int idx = i * 256 + tid;
        float4 v = __ldg(&xt[idx]);
        acc.x += v.x; acc.y += v.y; acc.z += v.z; acc.w += v.w;
        xb[idx] = make_uint2(bf16x2(v.x, v.y), bf16x2(v.z, v.w));
    }

    __shared__ float4 red[8][32];
    red[w8][l] = acc;
    __syncthreads();
    if (w8 == 0) {
        float4 t = red[0][l];
#pragma unroll
        for (int j = 1; j < 8; j++) {
            float4 a = red[j][l];
            t.x += a.x; t.y += a.y; t.z += a.z; t.w += a.w;
        }
        reinterpret_cast<float4*>(&g_partial[(size_t)(b * CHUNKS + chunk) * DIM])[l] = t;
    }
}

// ---------------------------------------------------------------------------
// Pass 2: blocks 0..31 -> pooled[b] (exact fp32); block 32 -> w1 frag image.
// ---------------------------------------------------------------------------
__global__ void __launch_bounds__(128)
prep_kernel(const float* __restrict__ w1, const float* __restrict__ w2,
            const float* __restrict__ bias) {
    const int t = threadIdx.x;
    if (blockIdx.x == 32) {
        const int lane = t & 31;
        const int n0 = lane >> 2;
        const int k0 = (lane & 3) * 2;
#pragma unroll 4
        for (int blk = t >> 5; blk < 64; blk += 4) {
            const int npair = blk >> 3, kstep = blk & 7;
            const int n = npair * 16 + n0;
            const int k = kstep * 16 + k0;
            uint4 v;
            v.x = bf16x2(w1[k * DIM + n],           w1[(k + 1) * DIM + n]);
            v.y = bf16x2(w1[(k + 8) * DIM + n],     w1[(k + 9) * DIM + n]);
            v.z = bf16x2(w1[k * DIM + n + 8],       w1[(k + 1) * DIM + n + 8]);
            v.w = bf16x2(w1[(k + 8) * DIM + n + 8], w1[(k + 9) * DIM + n + 8]);
            g_w1frag[blk * 32 + lane] = v;
        }
        return;
    }
    const int b = blockIdx.x;
    __shared__ float xs[DIM];
    float s = 0.f;
#pragma unroll 8
    for (int c = 0; c < CHUNKS; c++)
        s += g_partial[(size_t)(b * CHUNKS + c) * DIM + t];
    xs[t] = s;
    __syncthreads();
    float p = bias[t];
#pragma unroll 8
    for (int d = 0; d < DIM; d++)
        p += xs[d] * w2[d * DIM + t];
    g_pooled[b * DIM + t] = p;
}

// ---------------------------------------------------------------------------
// Pass 3: out = x @ w1 + pooled.  Multi-tile cp.async pipeline.
// grid (NSET/TILE_M/TILES_PER_CTA, BATCH) = (64, 32), 256 thr (8 warps, 2m x 4n).
// SMEM: double-buffered A tile (2 x 34816 = 69632 B).
// Per tile: wait -> sync -> prefetch(next) -> mainloop -> direct-frag store.
// ---------------------------------------------------------------------------
#define SMEM_BYTES (2 * ABUF)

DI void prefetch_tile(uint32_t dstbase, const uint4* __restrict__ src, int tid) {
#pragma unroll
    for (int i = 0; i < 8; i++) {
        const int idx = i * 256 + tid;              // 0..2047 uint4
        const uint32_t row = (uint32_t)idx >> 4, col8 = (uint32_t)idx & 15u;
        asm volatile("cp.async.cg.shared.global [%0], [%1], 16;"
                     :: "r"(dstbase + row * LDBYTES + col8 * 16u),
                        "l"(src + idx) : "memory");
    }
    asm volatile("cp.async.commit_group;" ::: "memory");
}

__global__ void __launch_bounds__(256, 2)
ell_main(float* __restrict__ out) {
    extern __shared__ char smem[];
    const uint32_t A0 = smem_u32(smem);

    const int tid = threadIdx.x, lane = tid & 31, wid = tid >> 5;
    const int wm = wid >> 2;   // 0..1
    const int wn = wid & 3;    // 0..3
    const int b = blockIdx.y;
    const int nt0 = blockIdx.x * TILES_PER_CTA;

    // --- pooled values for this lane's output columns (4 nf x 2 cols) ---
    float2 pv[4];
    {
        const float* pbase = g_pooled + b * DIM + wn * 32 + (lane & 3) * 2;
#pragma unroll
        for (int nf = 0; nf < 4; nf++)
            pv[nf] = __ldg(reinterpret_cast<const float2*>(pbase + nf * 8));
    }

    // tile base in uint4 units: one tile = 128 rows * 16 uint4
    const uint4* xb = reinterpret_cast<const uint4*>(g_xbf) +
                      ((size_t)(b * NSET + nt0 * TILE_M) >> 0) * 16;

    // prologue: prefetch tile 0 into buffer 0
    prefetch_tile(A0, xb, tid);

    const uint32_t lrow  = (uint32_t)(lane & 15);
    const uint32_t khalf = (uint32_t)(lane >> 4) * 16u;
    const uint4* Bb = g_w1frag + lane;              // + (npair*8 + k)*32

#pragma unroll
    for (int t = 0; t < TILES_PER_CTA; t++) {
        const uint32_t Abuf = A0 + (uint32_t)(t & 1) * ABUF;

        asm volatile("cp.async.wait_group 0;" ::: "memory");
        __syncthreads();

        if (t + 1 < TILES_PER_CTA)
            prefetch_tile(A0 + (uint32_t)((t + 1) & 1) * ABUF,
                          xb + (size_t)(t + 1) * 2048, tid);

        float c[4][4][4];
#pragma unroll
        for (int mf = 0; mf < 4; mf++)
#pragma unroll
            for (int nf = 0; nf < 4; nf++)
#pragma unroll
                for (int e = 0; e < 4; e++) c[mf][nf][e] = 0.f;

        uint32_t aBase[4];
#pragma unroll
        for (int mf = 0; mf < 4; mf++)
            aBase[mf] = Abuf + (wm * 64 + mf * 16 + lrow) * LDBYTES + khalf;

#pragma unroll
        for (int k = 0; k < 8; k++) {
            const uint32_t koff = (uint32_t)k * 32u;
            uint32_t a[4][4];
            uint4 bb[2];
#pragma unroll
            for (int mf = 0; mf < 4; mf++) LDSM_X4(a[mf], aBase[mf] + koff);
#pragma unroll
            for (int pp = 0; pp < 2; pp++)
                bb[pp] = __ldg(Bb + ((wn * 2 + pp) * 8 + k) * 32);
#pragma unroll
            for (int mf = 0; mf < 4; mf++) {
#pragma unroll
                for (int nf = 0; nf < 4; nf++) {
                    const int p = nf >> 1;
                    const uint32_t b0 = (nf & 1) ? bb[p].z : bb[p].x;
                    const uint32_t b1 = (nf & 1) ? bb[p].w : bb[p].y;
                    MMA16816(c[mf][nf], a[mf], b0, b1);
                }
            }
        }

        // --- Direct epilogue: frag pairs contiguous 8B; warp packs 32B sectors;
        //     overlaps with the in-flight cp.async of the next tile ---
        float* obase = out + (size_t)(b * NSET + (nt0 + t) * TILE_M) * DIM;
#pragma unroll
        for (int mf = 0; mf < 4; mf++) {
            const int r0 = wm * 64 + mf * 16 + (lane >> 2);
#pragma unroll
            for (int nf = 0; nf < 4; nf++) {
                const int col = wn * 32 + nf * 8 + (lane & 3) * 2;
                *reinterpret_cast<float2*>(obase + (size_t)r0 * DIM + col) =
                    make_float2(c[mf][nf][0] + pv[nf].x, c[mf][nf][1] + pv[nf].y);
                *reinterpret_cast<float2*>(obase + (size_t)(r0 + 8) * DIM + col) =
                    make_float2(c[mf][nf][2] + pv[nf].x, c[mf][nf][3] + pv[nf].y);
            }
        }
    }
}

// ---------------------------------------------------------------------------
// Launch
// ---------------------------------------------------------------------------
extern "C" void kernel_launch(void* const* d_in, const int* in_sizes, int n_in,
                              void* d_out, int out_size) {
    const float* x    = (const float*)d_in[0];
    const float* w1   = (const float*)d_in[1];
    const float* w2   = (const float*)d_in[2];
    const float* bias = (const float*)d_in[3];
    float* out = (float*)d_out;

    static bool attr_done = false;
    if (!attr_done) {
        cudaFuncSetAttribute(ell_main, cudaFuncAttributeMaxDynamicSharedMemorySize,
                             SMEM_BYTES);
        attr_done = true;
    }

    sum_cvt_kernel<<<dim3(CHUNKS, BATCH), 256>>>(x);
    prep_kernel<<<33, 128>>>(w1, w2, bias);
    ell_main<<<dim3(NSET / TILE_M / TILES_PER_CTA, BATCH), 256, SMEM_BYTES>>>(out);
}